// round 16
// baseline (speedup 1.0000x reference)
#include <cuda_runtime.h>
#include <cuda_bf16.h>
#include <math.h>
#include <stdint.h>

#define DIMV   256
#define HEADS  8
#define DHEAD  64
#define INNER  512
#define NN     6
#define QLEN   900
#define KLEN   1408
#define NK     (NN*KLEN)     // 8448
#define NQG    (NN*QLEN)     // 5400

#define BQ     64
#define BKT    64
#define LOG2E  1.4426950408889634f

// ---------------- scratch (device globals; no allocation allowed) ----------
__device__ __nv_bfloat16 gb_qg[NQG*INNER];
__device__ __nv_bfloat16 gb_kg[NK*INNER];
__device__ __nv_bfloat16 gb_ka[NK*INNER];
__device__ __nv_bfloat16 gb_qa[QLEN*INNER];
__device__ __nv_bfloat16 gb_vv[NK*INNER];
__device__ float g_z0[QLEN*DIMV];
__device__ float g_z1[QLEN*DIMV];
__device__ float g_z2[QLEN*DIMV];
__device__ float g_madd[NK];      // slot-based (compacted) additive mask
__device__ int   g_kidx[NK];      // slot -> original key row
__device__ int   g_ntiles[NN];    // padded 64-key tile count per n-group
// split-attention partials (max-free: only unnormalized O and L)
__device__ __nv_bfloat16 g_po_bf[NN*HEADS*QLEN*DHEAD];
__device__ float g_pl[NN*HEADS*QLEN];
// bf16 copies of raw inputs + projection weights
__device__ __nv_bfloat16 gbi_qg[NQG*DIMV];
__device__ __nv_bfloat16 gbi_qa[QLEN*DIMV];
__device__ __nv_bfloat16 gbi_kg[NK*DIMV];
__device__ __nv_bfloat16 gbi_ka[NK*DIMV];
__device__ __nv_bfloat16 gbi_v [NK*DIMV];
__device__ __nv_bfloat16 gbw_qg[DIMV*INNER];
__device__ __nv_bfloat16 gbw_kg[DIMV*INNER];
__device__ __nv_bfloat16 gbw_qa[DIMV*INNER];
__device__ __nv_bfloat16 gbw_ka[DIMV*INNER];
__device__ __nv_bfloat16 gbw_v [DIMV*INNER];
// hi/lo split operands for the accuracy-critical tail
__device__ __nv_bfloat16 ga_h[QLEN*INNER],  ga_l[QLEN*INNER];
__device__ __nv_bfloat16 gz1_h[QLEN*DIMV],  gz1_l[QLEN*DIMV];
__device__ __nv_bfloat16 gh1_h[QLEN*INNER], gh1_l[QLEN*INNER];
__device__ __nv_bfloat16 gwo_h[INNER*DIMV], gwo_l[INNER*DIMV];
__device__ __nv_bfloat16 gwm1_h[DIMV*INNER], gwm1_l[DIMV*INNER];
__device__ __nv_bfloat16 gwm2_h[INNER*DIMV], gwm2_l[INNER*DIMV];

// ---------------- PTX helpers ----------------------------------------------
__device__ __forceinline__ uint32_t s2u(const void* p) {
    return (uint32_t)__cvta_generic_to_shared(p);
}
__device__ __forceinline__ uint32_t packbf(float lo, float hi) {
    uint32_t d;
    asm("cvt.rn.bf16x2.f32 %0,%1,%2;" : "=r"(d) : "f"(hi), "f"(lo));
    return d;
}
__device__ __forceinline__ float2 unpackbf(uint32_t w) {
    __nv_bfloat162 t = *reinterpret_cast<__nv_bfloat162*>(&w);
    return make_float2(__bfloat162float(t.x), __bfloat162float(t.y));
}
#define LDSM4(d0,d1,d2,d3,a) \
    asm volatile("ldmatrix.sync.aligned.m8n8.x4.shared.b16 {%0,%1,%2,%3},[%4];" \
        : "=r"(d0),"=r"(d1),"=r"(d2),"=r"(d3) : "r"(a))
#define LDSM4T(d0,d1,d2,d3,a) \
    asm volatile("ldmatrix.sync.aligned.m8n8.x4.trans.shared.b16 {%0,%1,%2,%3},[%4];" \
        : "=r"(d0),"=r"(d1),"=r"(d2),"=r"(d3) : "r"(a))
#define MMA_BF16(c, a, b0, b1) \
    asm volatile("mma.sync.aligned.m16n8k16.row.col.f32.bf16.bf16.f32 " \
        "{%0,%1,%2,%3},{%4,%5,%6,%7},{%8,%9},{%0,%1,%2,%3};" \
        : "+f"((c)[0]),"+f"((c)[1]),"+f"((c)[2]),"+f"((c)[3]) \
        : "r"((a)[0]),"r"((a)[1]),"r"((a)[2]),"r"((a)[3]),"r"(b0),"r"(b1))
#define CPA16(dst,src) \
    asm volatile("cp.async.cg.shared.global [%0],[%1],16;" :: "r"(dst),"l"(src))
#define CPC()  asm volatile("cp.async.commit_group;")
#define CPW0() asm volatile("cp.async.wait_group 0;" ::: "memory")
#define CPW1() asm volatile("cp.async.wait_group 1;" ::: "memory")

// ---------------- cvt (+ split) + parallel mask compaction ------------------
#define NCVT 13
struct CvtTable {
    const float* src[NCVT];
    __nv_bfloat16* dst[NCVT];
    __nv_bfloat16* dstl[NCVT];
    int off[NCVT + 1];
};
__global__ __launch_bounds__(256) void cvt_kernel(CvtTable t,
                                                  const unsigned char* __restrict__ m)
{
    int tid = threadIdx.x;
    if (blockIdx.x >= gridDim.x - NN) {
        // ---- one block per n-group: sniff dtype (redundant) + compaction ----
        int n = blockIdx.x - (gridDim.x - NN);
        __shared__ int flags[2];
        __shared__ int scn[256];
        __shared__ int sdt;
        if (tid < 2) flags[tid] = 0;
        __syncthreads();
        int f1 = 0, f3 = 0;
        for (int i = tid; i < NK; i += 256) {
            unsigned char b = m[i];
            if (b) {
                if ((i & 3) == 1) f1 = 1;
                if ((i & 3) == 3) f3 = 1;
            }
        }
        if (f1) atomicOr(&flags[0], 1);
        if (f3) atomicOr(&flags[1], 1);
        __syncthreads();
        if (tid == 0) sdt = flags[0] ? 0 : (flags[1] ? 2 : 1);
        __syncthreads();
        int dt = sdt;   // 0=uint8, 1=int32, 2=float32

        int base = n * KLEN;
        int cs = tid * 6;
        int ce = cs + 6 > KLEN ? KLEN : cs + 6;
        bool um[6];
        int cnt = 0;
#pragma unroll
        for (int k = 0; k < 6; k++) um[k] = false;
        for (int i = cs; i < ce; i++) {
            int gi = base + i;
            bool msk;
            if (dt == 0)      msk = (m[gi] != 0);
            else if (dt == 1) msk = (((const int*)m)[gi] != 0);
            else              msk = (((const float*)m)[gi] != 0.0f);
            um[i - cs] = !msk;
            cnt += !msk;
        }
        scn[tid] = cnt;
        __syncthreads();
        for (int off = 1; off < 256; off <<= 1) {
            int v = (tid >= off) ? scn[tid - off] : 0;
            __syncthreads();
            scn[tid] += v;
            __syncthreads();
        }
        int total = scn[255];
        int p = scn[tid] - cnt;   // exclusive offset
        for (int i = cs; i < ce; i++) {
            if (um[i - cs]) g_kidx[base + p++] = base + i;
        }
        int padded = ((total + 63) >> 6) << 6;
        __syncthreads();
        for (int j = total + tid; j < padded; j += 256) g_kidx[base + j] = base;
        for (int j = tid; j < padded; j += 256)
            g_madd[base + j] = (j < total) ? 0.0f : -1e30f;
        if (tid == 0) g_ntiles[n] = padded >> 6;
        return;
    }
    int nb = gridDim.x - NN;
    int total = t.off[NCVT];
    for (int i = blockIdx.x * 256 + tid; i < total; i += nb * 256) {
        int e = 0;
        while (i >= t.off[e + 1]) e++;
        int j = i - t.off[e];
        float4 f = ((const float4*)t.src[e])[j];
        if (t.dstl[e] == nullptr) {
            ((uint2*)t.dst[e])[j] = make_uint2(packbf(f.x, f.y), packbf(f.z, f.w));
        } else {
            float h0 = __bfloat162float(__float2bfloat16(f.x));
            float h1 = __bfloat162float(__float2bfloat16(f.y));
            float h2 = __bfloat162float(__float2bfloat16(f.z));
            float h3 = __bfloat162float(__float2bfloat16(f.w));
            ((uint2*)t.dst[e])[j]  = make_uint2(packbf(h0, h1), packbf(h2, h3));
            ((uint2*)t.dstl[e])[j] = make_uint2(packbf(f.x - h0, f.y - h1),
                                                packbf(f.z - h2, f.w - h3));
        }
    }
}

// ---------------- pipelined bf16 projection GEMM (optional gather) ---------
struct PArg {
    const __nv_bfloat16* A;
    const __nv_bfloat16* W;
    const float* bias;
    const float* cs;
    float csmul;
    __nv_bfloat16* out;
    const int* kidx;
    const int* ntiles;
    int M;
};
#define PJ_STG 24576

__global__ __launch_bounds__(256) void proj_gemm_kernel(
    PArg p0, PArg p1, PArg p2, PArg p3, PArg p4)
{
    __shared__ __align__(16) char ps[2 * PJ_STG];
    PArg p = (blockIdx.z == 0) ? p0 : (blockIdx.z == 1) ? p1 :
             (blockIdx.z == 2) ? p2 : (blockIdx.z == 3) ? p3 : p4;
    int row0 = blockIdx.x * 128;
    if (row0 >= p.M) return;
    if (p.kidx) {
        int n = row0 / KLEN;
        int local = row0 - n * KLEN;
        if (local >= p.ntiles[n] * 64) return;
    }
    int col0 = blockIdx.y * 64;
    int tid = threadIdx.x, lane = tid & 31, warp = tid >> 5;
    int wm = warp >> 1, wn = warp & 1;
    const __nv_bfloat16* A = p.A;
    const __nv_bfloat16* W = p.W;
    int M = p.M;

    auto issue = [&](int st, int k0) {
        char* buf = ps + st * PJ_STG;
#pragma unroll
        for (int i = 0; i < 4; i++) {
            int s = tid + i * 256;
            int r = s >> 3, c = s & 7;
            int ar = row0 + r; if (ar > M - 1) ar = M - 1;
            if (p.kidx) ar = p.kidx[ar];
            CPA16(s2u(buf) + r * 128 + ((c ^ (r & 7)) << 4),
                  (const void*)(A + (size_t)ar * DIMV + k0 + c * 8));
        }
#pragma unroll
        for (int i = 0; i < 2; i++) {
            int s = tid + i * 256;
            int r = s >> 3, c = s & 7;
            CPA16(s2u(buf) + 16384 + r * 128 + ((c ^ (r & 7)) << 4),
                  (const void*)(W + (size_t)(k0 + r) * INNER + col0 + c * 8));
        }
    };

    float acc[2][4][4];
#pragma unroll
    for (int mt = 0; mt < 2; mt++)
#pragma unroll
        for (int j = 0; j < 4; j++)
#pragma unroll
            for (int x = 0; x < 4; x++) acc[mt][j][x] = 0.f;

    issue(0, 0);
    CPC();

#pragma unroll
    for (int kt = 0; kt < 4; kt++) {
        if (kt < 3) { issue((kt + 1) & 1, (kt + 1) * 64); CPC(); CPW1(); }
        else        { CPW0(); }
        __syncthreads();
        char* sA = ps + (kt & 1) * PJ_STG;
        char* sW = sA + 16384;
#pragma unroll
        for (int kk = 0; kk < 4; kk++) {
            uint32_t af[2][4];
#pragma unroll
            for (int mt = 0; mt < 2; mt++) {
                int r = wm * 32 + mt * 16 + (lane & 15);
                int koff = kk * 16 + ((lane & 16) ? 8 : 0);
                uint32_t a = s2u(sA) + r * 128 + (((koff >> 3) ^ (r & 7)) << 4);
                LDSM4(af[mt][0], af[mt][1], af[mt][2], af[mt][3], a);
            }
            uint32_t bf[4][2];
            int krow = kk * 16 + ((lane & 8) ? 8 : 0) + (lane & 7);
#pragma unroll
            for (int jj = 0; jj < 2; jj++) {
                int noff = wn * 32 + jj * 16 + ((lane & 16) ? 8 : 0);
                uint32_t ad = s2u(sW) + krow * 128 + (((noff >> 3) ^ (krow & 7)) << 4);
                LDSM4T(bf[2*jj][0], bf[2*jj][1], bf[2*jj+1][0], bf[2*jj+1][1], ad);
            }
#pragma unroll
            for (int mt = 0; mt < 2; mt++)
#pragma unroll
                for (int j = 0; j < 4; j++)
                    MMA_BF16(acc[mt][j], af[mt], bf[j][0], bf[j][1]);
        }
        __syncthreads();
    }

    int g = lane >> 2, c2 = (lane & 3) * 2;
#pragma unroll
    for (int mt = 0; mt < 2; mt++) {
        int r0 = row0 + wm * 32 + mt * 16 + g;
        int r1 = r0 + 8;
#pragma unroll
        for (int j = 0; j < 4; j++) {
            int col = col0 + wn * 32 + j * 8 + c2;
            float b0 = p.bias[col], b1 = p.bias[col + 1];
            float cs = (p.cs ? p.cs[col >> 6] : 1.0f) * p.csmul;
            if (r0 < M)
                *(uint32_t*)(p.out + (size_t)r0 * INNER + col) =
                    packbf((acc[mt][j][0] + b0) * cs, (acc[mt][j][1] + b1) * cs);
            if (r1 < M)
                *(uint32_t*)(p.out + (size_t)r1 * INNER + col) =
                    packbf((acc[mt][j][2] + b0) * cs, (acc[mt][j][3] + b1) * cs);
        }
    }
}

// ---------------- pipelined split-bf16 tail GEMM (256 threads) --------------
struct TArg {
    const __nv_bfloat16 *Ah, *Al, *Wh, *Wl;
    const float *bias, *res;
    float* Cf;
    __nv_bfloat16 *Ch, *Cl;
    int M, N, Kd, gelu;
};
#define TL_STG 32768

__global__ __launch_bounds__(256) void tail_gemm_kernel(TArg p)
{
    extern __shared__ char ts[];
    int tid = threadIdx.x, lane = tid & 31, warp = tid >> 5;
    int row0 = blockIdx.x * 64, col0 = blockIdx.y * 64;
    int wm = warp >> 1, wn = warp & 1;
    int nst = p.Kd >> 6;

    auto issue = [&](int st, int k0) {
        char* buf = ts + st * TL_STG;
#pragma unroll
        for (int i = 0; i < 2; i++) {
            int s = tid + i * 256;
            int r = s >> 3, c = s & 7;
            int ar = row0 + r; if (ar > p.M - 1) ar = p.M - 1;
            uint32_t doff = (uint32_t)(r * 128 + ((c ^ (r & 7)) << 4));
            size_t aoff = (size_t)ar * p.Kd + k0 + c * 8;
            size_t woff = (size_t)(k0 + r) * p.N + col0 + c * 8;
            CPA16(s2u(buf) + doff,         (const void*)(p.Ah + aoff));
            CPA16(s2u(buf) + 8192  + doff, (const void*)(p.Al + aoff));
            CPA16(s2u(buf) + 16384 + doff, (const void*)(p.Wh + woff));
            CPA16(s2u(buf) + 24576 + doff, (const void*)(p.Wl + woff));
        }
    };

    float acc[4][4];
#pragma unroll
    for (int j = 0; j < 4; j++)
#pragma unroll
        for (int x = 0; x < 4; x++) acc[j][x] = 0.f;

    issue(0, 0);
    CPC();

    for (int kt = 0; kt < nst; kt++) {
        if (kt + 1 < nst) { issue((kt + 1) & 1, (kt + 1) * 64); CPC(); CPW1(); }
        else              { CPW0(); }
        __syncthreads();
        char* sAh = ts + (kt & 1) * TL_STG;
        char* sAl = sAh + 8192;
        char* sWh = sAh + 16384;
        char* sWl = sAh + 24576;
#pragma unroll
        for (int kk = 0; kk < 4; kk++) {
            uint32_t ah[4], al[4];
            {
                int r = wm * 16 + (lane & 15);
                int koff = kk * 16 + ((lane & 16) ? 8 : 0);
                uint32_t sw = (uint32_t)(r * 128 + (((koff >> 3) ^ (r & 7)) << 4));
                LDSM4(ah[0], ah[1], ah[2], ah[3], s2u(sAh) + sw);
                LDSM4(al[0], al[1], al[2], al[3], s2u(sAl) + sw);
            }
            uint32_t wh[4][2], wl[4][2];
            int krow = kk * 16 + ((lane & 8) ? 8 : 0) + (lane & 7);
#pragma unroll
            for (int jj = 0; jj < 2; jj++) {
                int noff = wn * 32 + jj * 16 + ((lane & 16) ? 8 : 0);
                uint32_t sw = (uint32_t)(krow * 128 + (((noff >> 3) ^ (krow & 7)) << 4));
                LDSM4T(wh[2*jj][0], wh[2*jj][1], wh[2*jj+1][0], wh[2*jj+1][1], s2u(sWh) + sw);
                LDSM4T(wl[2*jj][0], wl[2*jj][1], wl[2*jj+1][0], wl[2*jj+1][1], s2u(sWl) + sw);
            }
#pragma unroll
            for (int j = 0; j < 4; j++) {
                MMA_BF16(acc[j], ah, wh[j][0], wh[j][1]);
                MMA_BF16(acc[j], ah, wl[j][0], wl[j][1]);
                MMA_BF16(acc[j], al, wh[j][0], wh[j][1]);
            }
        }
        __syncthreads();
    }

    int g = lane >> 2, c2 = (lane & 3) * 2;
    int rr[2];
    rr[0] = row0 + wm * 16 + g;
    rr[1] = rr[0] + 8;
#pragma unroll
    for (int j = 0; j < 4; j++) {
        int col = col0 + wn * 32 + j * 8 + c2;
        float b0 = p.bias[col], b1 = p.bias[col + 1];
#pragma unroll
        for (int half = 0; half < 2; half++) {
            int r = rr[half];
            if (r >= p.M) continue;
            float v0 = acc[j][2*half + 0] + b0;
            float v1 = acc[j][2*half + 1] + b1;
            if (p.gelu) {
                v0 = 0.5f * v0 * (1.0f + erff(v0 * 0.70710678118654752f));
                v1 = 0.5f * v1 * (1.0f + erff(v1 * 0.70710678118654752f));
            }
            if (p.res) {
                v0 += p.res[(size_t)r * p.N + col];
                v1 += p.res[(size_t)r * p.N + col + 1];
            }
            if (p.Cf)
                *(float2*)(p.Cf + (size_t)r * p.N + col) = make_float2(v0, v1);
            if (p.Ch) {
                float h0 = __bfloat162float(__float2bfloat16(v0));
                float h1 = __bfloat162float(__float2bfloat16(v1));
                *(uint32_t*)(p.Ch + (size_t)r * p.N + col) = packbf(v0, v1);
                *(uint32_t*)(p.Cl + (size_t)r * p.N + col) = packbf(v0 - h0, v1 - h1);
            }
        }
    }
}

// ---------------- bf16 HMMA flash cross-attention (compacted keys) ---------
// L computed on the FMA pipe (scalar row sums) instead of ones-MMA.
#define QG_OFF   0
#define QA_OFF   8192
#define BUF0_OFF 16384
#define BUF_SZ   24832
#define B_KG     0
#define B_KA     8192
#define B_V      16384
#define B_MADD   24576
#define ATTN_SMEM (16384 + 2*BUF_SZ)   // 66048

__global__ __launch_bounds__(128) void attn_mma_kernel()
{
    extern __shared__ char sm_[];
    char* qg_s = sm_ + QG_OFF;
    char* qa_s = sm_ + QA_OFF;

    int tid = threadIdx.x, lane = tid & 31, warp = tid >> 5;
    int h  = blockIdx.y;
    int q0 = blockIdx.x * BQ;
    int sp = blockIdx.z;           // n-split
    int kbase = sp * KLEN;
    int ntl = g_ntiles[sp];

#pragma unroll
    for (int i = 0; i < 4; i++) {
        int cidx = tid + i * 128;
        int r = cidx >> 3, c = cidx & 7;
        int q = q0 + r; if (q > QLEN - 1) q = QLEN - 1;
        uint32_t doff = (uint32_t)(r * 128 + ((c ^ (r & 7)) << 4));
        *(uint4*)(qa_s + doff) =
            *(const uint4*)(gb_qa + (size_t)q * INNER + h * DHEAD + c * 8);
        *(uint4*)(qg_s + doff) =
            *(const uint4*)(gb_qg + (size_t)(sp * QLEN + q) * INNER + h * DHEAD + c * 8);
    }

    auto issue = [&](char* buf, int t) {
        int r0 = kbase + t * BKT;
#pragma unroll
        for (int i = 0; i < 4; i++) {
            int cidx = tid + i * 128;
            int r = cidx >> 3, c = cidx & 7;
            uint32_t doff = (uint32_t)(r * 128 + ((c ^ (r & 7)) << 4));
            size_t goff = (size_t)(r0 + r) * INNER + h * DHEAD + c * 8;
            CPA16(s2u(buf) + B_KG + doff, (const void*)(gb_kg + goff));
            CPA16(s2u(buf) + B_KA + doff, (const void*)(gb_ka + goff));
            CPA16(s2u(buf) + B_V  + doff, (const void*)(gb_vv + goff));
        }
        if (tid < 16)
            CPA16(s2u(buf) + B_MADD + tid * 16, (const void*)(g_madd + r0 + tid * 4));
    };
    issue(sm_ + BUF0_OFF, 0);
    CPC();
    __syncthreads();

    uint32_t qa_f[4][4], qg_f[4][4];
    {
        int r = warp * 16 + (lane & 15);
#pragma unroll
        for (int kk = 0; kk < 4; kk++) {
            int koff = kk * 16 + ((lane & 16) ? 8 : 0);
            uint32_t sw = (uint32_t)(r * 128 + (((koff >> 3) ^ (r & 7)) << 4));
            LDSM4(qa_f[kk][0], qa_f[kk][1], qa_f[kk][2], qa_f[kk][3], s2u(qa_s) + sw);
            LDSM4(qg_f[kk][0], qg_f[kk][1], qg_f[kk][2], qg_f[kk][3], s2u(qg_s) + sw);
        }
    }

    float o[8][4];
#pragma unroll
    for (int j = 0; j < 8; j++)
#pragma unroll
        for (int x = 0; x < 4; x++) o[j][x] = 0.f;
    float l0 = 0.f, l1 = 0.f;   // row sums (fma pipe)

    for (int t = 0; t < ntl; t++) {
        char* cbuf = sm_ + BUF0_OFF + (t & 1) * BUF_SZ;
        char* nbuf = sm_ + BUF0_OFF + ((t + 1) & 1) * BUF_SZ;

        if (t + 1 < ntl) { issue(nbuf, t + 1); CPC(); CPW1(); }
        else             { CPW0(); }
        __syncthreads();

        uint32_t kgb = s2u(cbuf) + B_KG;
        uint32_t kab = s2u(cbuf) + B_KA;
        uint32_t vb  = s2u(cbuf) + B_V;

        float s[8][4];
#pragma unroll
        for (int j = 0; j < 8; j++)
#pragma unroll
            for (int x = 0; x < 4; x++) s[j][x] = 0.f;

        int koff_b = ((lane & 8) ? 8 : 0);
        int nbase  = ((lane & 16) ? 8 : 0) + (lane & 7);
#pragma unroll
        for (int kk = 0; kk < 4; kk++) {
            int koff = kk * 16 + koff_b;
            uint32_t b[8][2];
#pragma unroll
            for (int jj = 0; jj < 4; jj++) {
                int n = jj * 16 + nbase;
                uint32_t a = kgb + n * 128 + (((koff >> 3) ^ (n & 7)) << 4);
                LDSM4(b[2*jj][0], b[2*jj][1], b[2*jj+1][0], b[2*jj+1][1], a);
            }
#pragma unroll
            for (int j = 0; j < 8; j++) MMA_BF16(s[j], qg_f[kk], b[j][0], b[j][1]);
#pragma unroll
            for (int jj = 0; jj < 4; jj++) {
                int n = jj * 16 + nbase;
                uint32_t a = kab + n * 128 + (((koff >> 3) ^ (n & 7)) << 4);
                LDSM4(b[2*jj][0], b[2*jj][1], b[2*jj+1][0], b[2*jj+1][1], a);
            }
#pragma unroll
            for (int j = 0; j < 8; j++) MMA_BF16(s[j], qa_f[kk], b[j][0], b[j][1]);
        }

        const float* madd = (const float*)(cbuf + B_MADD);
        int c0 = (lane & 3) * 2;
#pragma unroll
        for (int j = 0; j < 8; j++) {
            float2 md = *(const float2*)(madd + 8 * j + c0);
            s[j][0] = exp2f(s[j][0] + md.x);
            s[j][1] = exp2f(s[j][1] + md.y);
            s[j][2] = exp2f(s[j][2] + md.x);
            s[j][3] = exp2f(s[j][3] + md.y);
            l0 += s[j][0] + s[j][1];
            l1 += s[j][2] + s[j][3];
        }

        int nb = ((lane & 16) ? 8 : 0);
#pragma unroll
        for (int kk = 0; kk < 4; kk++) {
            uint32_t a[4];
            a[0] = packbf(s[2*kk][0],   s[2*kk][1]);
            a[1] = packbf(s[2*kk][2],   s[2*kk][3]);
            a[2] = packbf(s[2*kk+1][0], s[2*kk+1][1]);
            a[3] = packbf(s[2*kk+1][2], s[2*kk+1][3]);
            int krow = kk * 16 + ((lane & 8) ? 8 : 0) + (lane & 7);
            uint32_t b[8][2];
#pragma unroll
            for (int jj = 0; jj < 4; jj++) {
                int noff = jj * 16 + nb;
                uint32_t ad = vb + krow * 128 + (((noff >> 3) ^ (krow & 7)) << 4);
                LDSM4T(b[2*jj][0], b[2*jj][1], b[2*jj+1][0], b[2*jj+1][1], ad);
            }
#pragma unroll
            for (int j = 0; j < 8; j++) MMA_BF16(o[j], a, b[j][0], b[j][1]);
        }
        __syncthreads();
    }

    // quad-reduce L (8 lanes per row-pair share via xor 1,2)
    l0 += __shfl_xor_sync(0xffffffffu, l0, 1);
    l0 += __shfl_xor_sync(0xffffffffu, l0, 2);
    l1 += __shfl_xor_sync(0xffffffffu, l1, 1);
    l1 += __shfl_xor_sync(0xffffffffu, l1, 2);

    int g = lane >> 2, c0 = (lane & 3) * 2;
    int r0q = q0 + warp * 16 + g;
    int r1q = r0q + 8;
    __nv_bfloat16* po = g_po_bf + (size_t)((sp * HEADS + h) * QLEN) * DHEAD;
    float* pl = g_pl + (sp * HEADS + h) * QLEN;
    if (r0q < QLEN) {
#pragma unroll
        for (int j = 0; j < 8; j++)
            *(uint32_t*)(po + (size_t)r0q * DHEAD + 8 * j + c0) =
                packbf(o[j][0], o[j][1]);
        if ((lane & 3) == 0) pl[r0q] = l0;
    }
    if (r1q < QLEN) {
#pragma unroll
        for (int j = 0; j < 8; j++)
            *(uint32_t*)(po + (size_t)r1q * DHEAD + 8 * j + c0) =
                packbf(o[j][2], o[j][3]);
        if ((lane & 3) == 0) pl[r1q] = l1;
    }
}

// ---------------- combine partials (fine-grained) -> att hi/lo bf16 --------
// one thread per 4-element d-chunk: 900*8*16 = 115200 threads.
__global__ __launch_bounds__(128) void combine_kernel()
{
    int gt = blockIdx.x * 128 + threadIdx.x;
    if (gt >= QLEN * HEADS * 16) return;
    int q  = gt >> 7;
    int r  = gt & 127;
    int h  = r >> 4;
    int ch = r & 15;

    float O[4] = {0.f, 0.f, 0.f, 0.f};
    float L = 0.f;
#pragma unroll
    for (int s = 0; s < NN; s++) {
        int idx = (s * HEADS + h) * QLEN + q;
        L += g_pl[idx];
        uint2 w = *(const uint2*)(g_po_bf + (size_t)idx * DHEAD + ch * 4);
        float2 f;
        f = unpackbf(w.x); O[0] += f.x; O[1] += f.y;
        f = unpackbf(w.y); O[2] += f.x; O[3] += f.y;
    }
    float inv = 1.0f / L;
    uint32_t hw[2], lw[2];
#pragma unroll
    for (int i = 0; i < 2; i++) {
        float v0 = O[2*i] * inv, v1 = O[2*i+1] * inv;
        float h0 = __bfloat162float(__float2bfloat16(v0));
        float h1 = __bfloat162float(__float2bfloat16(v1));
        hw[i] = packbf(v0, v1);
        lw[i] = packbf(v0 - h0, v1 - h1);
    }
    size_t oidx = (size_t)q * INNER + h * DHEAD + ch * 4;
    *(uint2*)(ga_h + oidx) = make_uint2(hw[0], hw[1]);
    *(uint2*)(ga_l + oidx) = make_uint2(lw[0], lw[1]);
}

// ---------------- LayerNorm (optional hi/lo bf16 side output) --------------
__global__ __launch_bounds__(256) void ln_kernel(
    const float* __restrict__ x, const float* __restrict__ g,
    const float* __restrict__ b, float* __restrict__ y,
    __nv_bfloat16* __restrict__ yh, __nv_bfloat16* __restrict__ yl)
{
    int row = blockIdx.x;
    int tid = threadIdx.x;
    float v = x[(size_t)row * DIMV + tid];
    float s = v, s2 = v * v;
#pragma unroll
    for (int off = 16; off > 0; off >>= 1) {
        s  += __shfl_xor_sync(0xffffffffu, s, off);
        s2 += __shfl_xor_sync(0xffffffffu, s2, off);
    }
    __shared__ float rs[8], rs2[8];
    int w = tid >> 5;
    if ((tid & 31) == 0) { rs[w] = s; rs2[w] = s2; }
    __syncthreads();
    float ts = 0.f, ts2 = 0.f;
#pragma unroll
    for (int i = 0; i < 8; i++) { ts += rs[i]; ts2 += rs2[i]; }
    float mean = ts * (1.0f / DIMV);
    float var  = ts2 * (1.0f / DIMV) - mean * mean;
    float val = (v - mean) * rsqrtf(var + 1e-5f) * g[tid] + b[tid];
    y[(size_t)row * DIMV + tid] = val;
    if (yh) {
        __nv_bfloat16 hi = __float2bfloat16(val);
        yh[(size_t)row * DIMV + tid] = hi;
        yl[(size_t)row * DIMV + tid] = __float2bfloat16(val - __bfloat162float(hi));
    }
}

// ---------------- launcher ------------------------------------------------
extern "C" void kernel_launch(void* const* d_in, const int* in_sizes, int n_in,
                              void* d_out, int out_size)
{
    (void)in_sizes; (void)n_in; (void)out_size;
    const float* k_g  = (const float*)d_in[0];
    const float* q_g  = (const float*)d_in[1];
    const float* k_a  = (const float*)d_in[2];
    const float* q_a  = (const float*)d_in[3];
    const float* v    = (const float*)d_in[4];
    const unsigned char* mask = (const unsigned char*)d_in[5];
    const float* W_qg = (const float*)d_in[6];
    const float* b_qg = (const float*)d_in[7];
    const float* W_kg = (const float*)d_in[8];
    const float* b_kg = (const float*)d_in[9];
    const float* W_qa = (const float*)d_in[10];
    const float* b_qa = (const float*)d_in[11];
    const float* W_ka = (const float*)d_in[12];
    const float* b_ka = (const float*)d_in[13];
    const float* W_v  = (const float*)d_in[14];
    const float* b_v  = (const float*)d_in[15];
    const float* W_o  = (const float*)d_in[16];
    const float* b_o  = (const float*)d_in[17];
    const float* ln1_g = (const float*)d_in[18];
    const float* ln1_b = (const float*)d_in[19];
    const float* W_m1 = (const float*)d_in[20];
    const float* b_m1 = (const float*)d_in[21];
    const float* W_m2 = (const float*)d_in[22];
    const float* b_m2 = (const float*)d_in[23];
    const float* ln2_g = (const float*)d_in[24];
    const float* ln2_b = (const float*)d_in[25];
    const float* scale_g = (const float*)d_in[26];
    const float* scale_a = (const float*)d_in[27];
    float* out = (float*)d_out;

    __nv_bfloat16 *pb_qg, *pb_kg, *pb_ka, *pb_qa, *pb_vv;
    __nv_bfloat16 *pi_qg, *pi_qa, *pi_kg, *pi_ka, *pi_v;
    __nv_bfloat16 *pw_qg, *pw_kg, *pw_qa, *pw_ka, *pw_v;
    __nv_bfloat16 *pah, *pal, *pz1h, *pz1l, *ph1h, *ph1l;
    __nv_bfloat16 *pwoh, *pwol, *pwm1h, *pwm1l, *pwm2h, *pwm2l;
    float *p_z0, *p_z1, *p_z2;
    int *p_kidx, *p_ntl;
    cudaGetSymbolAddress((void**)&pb_qg, gb_qg);
    cudaGetSymbolAddress((void**)&pb_kg, gb_kg);
    cudaGetSymbolAddress((void**)&pb_ka, gb_ka);
    cudaGetSymbolAddress((void**)&pb_qa, gb_qa);
    cudaGetSymbolAddress((void**)&pb_vv, gb_vv);
    cudaGetSymbolAddress((void**)&pi_qg, gbi_qg);
    cudaGetSymbolAddress((void**)&pi_qa, gbi_qa);
    cudaGetSymbolAddress((void**)&pi_kg, gbi_kg);
    cudaGetSymbolAddress((void**)&pi_ka, gbi_ka);
    cudaGetSymbolAddress((void**)&pi_v,  gbi_v);
    cudaGetSymbolAddress((void**)&pw_qg, gbw_qg);
    cudaGetSymbolAddress((void**)&pw_kg, gbw_kg);
    cudaGetSymbolAddress((void**)&pw_qa, gbw_qa);
    cudaGetSymbolAddress((void**)&pw_ka, gbw_ka);
    cudaGetSymbolAddress((void**)&pw_v,  gbw_v);
    cudaGetSymbolAddress((void**)&pah,   ga_h);
    cudaGetSymbolAddress((void**)&pal,   ga_l);
    cudaGetSymbolAddress((void**)&pz1h,  gz1_h);
    cudaGetSymbolAddress((void**)&pz1l,  gz1_l);
    cudaGetSymbolAddress((void**)&ph1h,  gh1_h);
    cudaGetSymbolAddress((void**)&ph1l,  gh1_l);
    cudaGetSymbolAddress((void**)&pwoh,  gwo_h);
    cudaGetSymbolAddress((void**)&pwol,  gwo_l);
    cudaGetSymbolAddress((void**)&pwm1h, gwm1_h);
    cudaGetSymbolAddress((void**)&pwm1l, gwm1_l);
    cudaGetSymbolAddress((void**)&pwm2h, gwm2_h);
    cudaGetSymbolAddress((void**)&pwm2l, gwm2_l);
    cudaGetSymbolAddress((void**)&p_z0,  g_z0);
    cudaGetSymbolAddress((void**)&p_z1,  g_z1);
    cudaGetSymbolAddress((void**)&p_z2,  g_z2);
    cudaGetSymbolAddress((void**)&p_kidx, g_kidx);
    cudaGetSymbolAddress((void**)&p_ntl,  g_ntiles);

    dim3 blk(256);

    CvtTable ct;
    const float* srcs[NCVT]   = {q_g, q_a, k_g, k_a, v,
                                 W_qg, W_kg, W_qa, W_ka, W_v,
                                 W_o, W_m1, W_m2};
    __nv_bfloat16* dsts[NCVT] = {pi_qg, pi_qa, pi_kg, pi_ka, pi_v,
                                 pw_qg, pw_kg, pw_qa, pw_ka, pw_v,
                                 pwoh, pwm1h, pwm2h};
    __nv_bfloat16* dstl[NCVT] = {nullptr, nullptr, nullptr, nullptr, nullptr,
                                 nullptr, nullptr, nullptr, nullptr, nullptr,
                                 pwol, pwm1l, pwm2l};
    int sizes4[NCVT] = {NQG*DIMV/4, QLEN*DIMV/4, NK*DIMV/4, NK*DIMV/4, NK*DIMV/4,
                        DIMV*INNER/4, DIMV*INNER/4, DIMV*INNER/4, DIMV*INNER/4, DIMV*INNER/4,
                        INNER*DIMV/4, DIMV*INNER/4, INNER*DIMV/4};
    ct.off[0] = 0;
    for (int i = 0; i < NCVT; i++) {
        ct.src[i]  = srcs[i];
        ct.dst[i]  = dsts[i];
        ct.dstl[i] = dstl[i];
        ct.off[i+1] = ct.off[i] + sizes4[i];
    }
    cvt_kernel<<<4352 + NN, blk>>>(ct, mask);

    {
        PArg a0 = {pi_kg, pw_kg, b_kg, nullptr, 1.0f,  pb_kg, p_kidx, p_ntl, NK};
        PArg a1 = {pi_ka, pw_ka, b_ka, nullptr, 1.0f,  pb_ka, p_kidx, p_ntl, NK};
        PArg a2 = {pi_v,  pw_v,  b_v,  nullptr, 1.0f,  pb_vv, p_kidx, p_ntl, NK};
        PArg a3 = {pi_qg, pw_qg, b_qg, scale_g, LOG2E, pb_qg, nullptr, nullptr, NQG};
        PArg a4 = {pi_qa, pw_qa, b_qa, scale_a, LOG2E, pb_qa, nullptr, nullptr, QLEN};
        proj_gemm_kernel<<<dim3(NK/128, INNER/64, 5), blk>>>(a0, a1, a2, a3, a4);
    }

    cudaFuncSetAttribute(attn_mma_kernel, cudaFuncAttributeMaxDynamicSharedMemorySize, ATTN_SMEM);
    attn_mma_kernel<<<dim3((QLEN + BQ - 1) / BQ, HEADS, NN), 128, ATTN_SMEM>>>();
    combine_kernel<<<(QLEN * HEADS * 16 + 127) / 128, 128>>>();

    cudaFuncSetAttribute(tail_gemm_kernel, cudaFuncAttributeMaxDynamicSharedMemorySize, 2 * TL_STG);
    {
        TArg t1 = {pah, pal, pwoh, pwol, b_o, q_a, p_z0, nullptr, nullptr,
                   QLEN, DIMV, INNER, 0};
        tail_gemm_kernel<<<dim3((QLEN + 63)/64, DIMV/64), blk, 2 * TL_STG>>>(t1);
    }
    ln_kernel<<<QLEN, DIMV>>>(p_z0, ln1_g, ln1_b, p_z1, pz1h, pz1l);
    {
        TArg t2 = {pz1h, pz1l, pwm1h, pwm1l, b_m1, nullptr, nullptr, ph1h, ph1l,
                   QLEN, INNER, DIMV, 1};
        tail_gemm_kernel<<<dim3((QLEN + 63)/64, INNER/64), blk, 2 * TL_STG>>>(t2);
    }
    {
        TArg t3 = {ph1h, ph1l, pwm2h, pwm2l, b_m2, p_z1, p_z2, nullptr, nullptr,
                   QLEN, DIMV, INNER, 0};
        tail_gemm_kernel<<<dim3((QLEN + 63)/64, DIMV/64), blk, 2 * TL_STG>>>(t3);
    }
    ln_kernel<<<QLEN, DIMV>>>(p_z2, ln2_g, ln2_b, out, nullptr, nullptr);
}

// round 17
// speedup vs baseline: 1.0314x; 1.0314x over previous
#include <cuda_runtime.h>
#include <cuda_bf16.h>
#include <math.h>
#include <stdint.h>

#define DIMV   256
#define HEADS  8
#define DHEAD  64
#define INNER  512
#define NN     6
#define QLEN   900
#define KLEN   1408
#define NK     (NN*KLEN)     // 8448
#define NQG    (NN*QLEN)     // 5400

#define BQ     64
#define BKT    64
#define LOG2E  1.4426950408889634f

// ---------------- scratch (device globals; no allocation allowed) ----------
__device__ __nv_bfloat16 gb_qg[NQG*INNER];
__device__ __nv_bfloat16 gb_kg[NK*INNER];
__device__ __nv_bfloat16 gb_ka[NK*INNER];
__device__ __nv_bfloat16 gb_qa[QLEN*INNER];
__device__ __nv_bfloat16 gb_vv[NK*INNER];
__device__ float g_z0[QLEN*DIMV];
__device__ float g_z1[QLEN*DIMV];
__device__ float g_z2[QLEN*DIMV];
__device__ float g_madd[NK];      // slot-based (compacted) additive mask
__device__ int   g_kidx[NK];      // slot -> original key row
__device__ int   g_ntiles[NN];    // padded 64-key tile count per n-group
// split-attention partials (max-free: only unnormalized O and L)
__device__ __nv_bfloat16 g_po_bf[NN*HEADS*QLEN*DHEAD];
__device__ float g_pl[NN*HEADS*QLEN];
// bf16 copies of raw inputs + projection weights
__device__ __nv_bfloat16 gbi_qg[NQG*DIMV];
__device__ __nv_bfloat16 gbi_qa[QLEN*DIMV];
__device__ __nv_bfloat16 gbi_kg[NK*DIMV];
__device__ __nv_bfloat16 gbi_ka[NK*DIMV];
__device__ __nv_bfloat16 gbi_v [NK*DIMV];
__device__ __nv_bfloat16 gbw_qg[DIMV*INNER];
__device__ __nv_bfloat16 gbw_kg[DIMV*INNER];
__device__ __nv_bfloat16 gbw_qa[DIMV*INNER];
__device__ __nv_bfloat16 gbw_ka[DIMV*INNER];
__device__ __nv_bfloat16 gbw_v [DIMV*INNER];
// hi/lo split operands for the accuracy-critical tail
__device__ __nv_bfloat16 ga_h[QLEN*INNER],  ga_l[QLEN*INNER];
__device__ __nv_bfloat16 gz1_h[QLEN*DIMV],  gz1_l[QLEN*DIMV];
__device__ __nv_bfloat16 gh1_h[QLEN*INNER], gh1_l[QLEN*INNER];
__device__ __nv_bfloat16 gwo_h[INNER*DIMV], gwo_l[INNER*DIMV];
__device__ __nv_bfloat16 gwm1_h[DIMV*INNER], gwm1_l[DIMV*INNER];
__device__ __nv_bfloat16 gwm2_h[INNER*DIMV], gwm2_l[INNER*DIMV];

// ---------------- PTX helpers ----------------------------------------------
__device__ __forceinline__ uint32_t s2u(const void* p) {
    return (uint32_t)__cvta_generic_to_shared(p);
}
__device__ __forceinline__ uint32_t packbf(float lo, float hi) {
    uint32_t d;
    asm("cvt.rn.bf16x2.f32 %0,%1,%2;" : "=r"(d) : "f"(hi), "f"(lo));
    return d;
}
__device__ __forceinline__ float2 unpackbf(uint32_t w) {
    __nv_bfloat162 t = *reinterpret_cast<__nv_bfloat162*>(&w);
    return make_float2(__bfloat162float(t.x), __bfloat162float(t.y));
}
#define LDSM4(d0,d1,d2,d3,a) \
    asm volatile("ldmatrix.sync.aligned.m8n8.x4.shared.b16 {%0,%1,%2,%3},[%4];" \
        : "=r"(d0),"=r"(d1),"=r"(d2),"=r"(d3) : "r"(a))
#define LDSM4T(d0,d1,d2,d3,a) \
    asm volatile("ldmatrix.sync.aligned.m8n8.x4.trans.shared.b16 {%0,%1,%2,%3},[%4];" \
        : "=r"(d0),"=r"(d1),"=r"(d2),"=r"(d3) : "r"(a))
#define MMA_BF16(c, a, b0, b1) \
    asm volatile("mma.sync.aligned.m16n8k16.row.col.f32.bf16.bf16.f32 " \
        "{%0,%1,%2,%3},{%4,%5,%6,%7},{%8,%9},{%0,%1,%2,%3};" \
        : "+f"((c)[0]),"+f"((c)[1]),"+f"((c)[2]),"+f"((c)[3]) \
        : "r"((a)[0]),"r"((a)[1]),"r"((a)[2]),"r"((a)[3]),"r"(b0),"r"(b1))
#define CPA16(dst,src) \
    asm volatile("cp.async.cg.shared.global [%0],[%1],16;" :: "r"(dst),"l"(src))
#define CPC()  asm volatile("cp.async.commit_group;")
#define CPW0() asm volatile("cp.async.wait_group 0;" ::: "memory")
#define CPW1() asm volatile("cp.async.wait_group 1;" ::: "memory")

// ---------------- cvt (+ split) + parallel mask compaction ------------------
#define NCVT 13
struct CvtTable {
    const float* src[NCVT];
    __nv_bfloat16* dst[NCVT];
    __nv_bfloat16* dstl[NCVT];
    int off[NCVT + 1];
};
__global__ __launch_bounds__(256) void cvt_kernel(CvtTable t,
                                                  const unsigned char* __restrict__ m)
{
    int tid = threadIdx.x;
    if (blockIdx.x >= gridDim.x - NN) {
        // ---- one block per n-group: sniff dtype (redundant) + compaction ----
        int n = blockIdx.x - (gridDim.x - NN);
        __shared__ int flags[2];
        __shared__ int scn[256];
        __shared__ int sdt;
        if (tid < 2) flags[tid] = 0;
        __syncthreads();
        int f1 = 0, f3 = 0;
        for (int i = tid; i < NK; i += 256) {
            unsigned char b = m[i];
            if (b) {
                if ((i & 3) == 1) f1 = 1;
                if ((i & 3) == 3) f3 = 1;
            }
        }
        if (f1) atomicOr(&flags[0], 1);
        if (f3) atomicOr(&flags[1], 1);
        __syncthreads();
        if (tid == 0) sdt = flags[0] ? 0 : (flags[1] ? 2 : 1);
        __syncthreads();
        int dt = sdt;   // 0=uint8, 1=int32, 2=float32

        int base = n * KLEN;
        int cs = tid * 6;
        int ce = cs + 6 > KLEN ? KLEN : cs + 6;
        bool um[6];
        int cnt = 0;
#pragma unroll
        for (int k = 0; k < 6; k++) um[k] = false;
        for (int i = cs; i < ce; i++) {
            int gi = base + i;
            bool msk;
            if (dt == 0)      msk = (m[gi] != 0);
            else if (dt == 1) msk = (((const int*)m)[gi] != 0);
            else              msk = (((const float*)m)[gi] != 0.0f);
            um[i - cs] = !msk;
            cnt += !msk;
        }
        scn[tid] = cnt;
        __syncthreads();
        for (int off = 1; off < 256; off <<= 1) {
            int v = (tid >= off) ? scn[tid - off] : 0;
            __syncthreads();
            scn[tid] += v;
            __syncthreads();
        }
        int total = scn[255];
        int p = scn[tid] - cnt;   // exclusive offset
        for (int i = cs; i < ce; i++) {
            if (um[i - cs]) g_kidx[base + p++] = base + i;
        }
        int padded = ((total + 63) >> 6) << 6;
        __syncthreads();
        for (int j = total + tid; j < padded; j += 256) g_kidx[base + j] = base;
        for (int j = tid; j < padded; j += 256)
            g_madd[base + j] = (j < total) ? 0.0f : -1e30f;
        if (tid == 0) g_ntiles[n] = padded >> 6;
        return;
    }
    int nb = gridDim.x - NN;
    int total = t.off[NCVT];
    for (int i = blockIdx.x * 256 + tid; i < total; i += nb * 256) {
        int e = 0;
        while (i >= t.off[e + 1]) e++;
        int j = i - t.off[e];
        float4 f = ((const float4*)t.src[e])[j];
        if (t.dstl[e] == nullptr) {
            ((uint2*)t.dst[e])[j] = make_uint2(packbf(f.x, f.y), packbf(f.z, f.w));
        } else {
            float h0 = __bfloat162float(__float2bfloat16(f.x));
            float h1 = __bfloat162float(__float2bfloat16(f.y));
            float h2 = __bfloat162float(__float2bfloat16(f.z));
            float h3 = __bfloat162float(__float2bfloat16(f.w));
            ((uint2*)t.dst[e])[j]  = make_uint2(packbf(h0, h1), packbf(h2, h3));
            ((uint2*)t.dstl[e])[j] = make_uint2(packbf(f.x - h0, f.y - h1),
                                                packbf(f.z - h2, f.w - h3));
        }
    }
}

// ---------------- pipelined bf16 projection GEMM (optional gather) ---------
struct PArg {
    const __nv_bfloat16* A;
    const __nv_bfloat16* W;
    const float* bias;
    const float* cs;
    float csmul;
    __nv_bfloat16* out;
    const int* kidx;
    const int* ntiles;
    int M;
};
#define PJ_STG 24576

__global__ __launch_bounds__(256) void proj_gemm_kernel(
    PArg p0, PArg p1, PArg p2, PArg p3, PArg p4)
{
    __shared__ __align__(16) char ps[2 * PJ_STG];
    PArg p = (blockIdx.z == 0) ? p0 : (blockIdx.z == 1) ? p1 :
             (blockIdx.z == 2) ? p2 : (blockIdx.z == 3) ? p3 : p4;
    int row0 = blockIdx.x * 128;
    if (row0 >= p.M) return;
    if (p.kidx) {
        int n = row0 / KLEN;
        int local = row0 - n * KLEN;
        if (local >= p.ntiles[n] * 64) return;
    }
    int col0 = blockIdx.y * 64;
    int tid = threadIdx.x, lane = tid & 31, warp = tid >> 5;
    int wm = warp >> 1, wn = warp & 1;
    const __nv_bfloat16* A = p.A;
    const __nv_bfloat16* W = p.W;
    int M = p.M;

    auto issue = [&](int st, int k0) {
        char* buf = ps + st * PJ_STG;
#pragma unroll
        for (int i = 0; i < 4; i++) {
            int s = tid + i * 256;
            int r = s >> 3, c = s & 7;
            int ar = row0 + r; if (ar > M - 1) ar = M - 1;
            if (p.kidx) ar = p.kidx[ar];
            CPA16(s2u(buf) + r * 128 + ((c ^ (r & 7)) << 4),
                  (const void*)(A + (size_t)ar * DIMV + k0 + c * 8));
        }
#pragma unroll
        for (int i = 0; i < 2; i++) {
            int s = tid + i * 256;
            int r = s >> 3, c = s & 7;
            CPA16(s2u(buf) + 16384 + r * 128 + ((c ^ (r & 7)) << 4),
                  (const void*)(W + (size_t)(k0 + r) * INNER + col0 + c * 8));
        }
    };

    float acc[2][4][4];
#pragma unroll
    for (int mt = 0; mt < 2; mt++)
#pragma unroll
        for (int j = 0; j < 4; j++)
#pragma unroll
            for (int x = 0; x < 4; x++) acc[mt][j][x] = 0.f;

    issue(0, 0);
    CPC();

#pragma unroll
    for (int kt = 0; kt < 4; kt++) {
        if (kt < 3) { issue((kt + 1) & 1, (kt + 1) * 64); CPC(); CPW1(); }
        else        { CPW0(); }
        __syncthreads();
        char* sA = ps + (kt & 1) * PJ_STG;
        char* sW = sA + 16384;
#pragma unroll
        for (int kk = 0; kk < 4; kk++) {
            uint32_t af[2][4];
#pragma unroll
            for (int mt = 0; mt < 2; mt++) {
                int r = wm * 32 + mt * 16 + (lane & 15);
                int koff = kk * 16 + ((lane & 16) ? 8 : 0);
                uint32_t a = s2u(sA) + r * 128 + (((koff >> 3) ^ (r & 7)) << 4);
                LDSM4(af[mt][0], af[mt][1], af[mt][2], af[mt][3], a);
            }
            uint32_t bf[4][2];
            int krow = kk * 16 + ((lane & 8) ? 8 : 0) + (lane & 7);
#pragma unroll
            for (int jj = 0; jj < 2; jj++) {
                int noff = wn * 32 + jj * 16 + ((lane & 16) ? 8 : 0);
                uint32_t ad = s2u(sW) + krow * 128 + (((noff >> 3) ^ (krow & 7)) << 4);
                LDSM4T(bf[2*jj][0], bf[2*jj][1], bf[2*jj+1][0], bf[2*jj+1][1], ad);
            }
#pragma unroll
            for (int mt = 0; mt < 2; mt++)
#pragma unroll
                for (int j = 0; j < 4; j++)
                    MMA_BF16(acc[mt][j], af[mt], bf[j][0], bf[j][1]);
        }
        __syncthreads();
    }

    int g = lane >> 2, c2 = (lane & 3) * 2;
#pragma unroll
    for (int mt = 0; mt < 2; mt++) {
        int r0 = row0 + wm * 32 + mt * 16 + g;
        int r1 = r0 + 8;
#pragma unroll
        for (int j = 0; j < 4; j++) {
            int col = col0 + wn * 32 + j * 8 + c2;
            float b0 = p.bias[col], b1 = p.bias[col + 1];
            float cs = (p.cs ? p.cs[col >> 6] : 1.0f) * p.csmul;
            if (r0 < M)
                *(uint32_t*)(p.out + (size_t)r0 * INNER + col) =
                    packbf((acc[mt][j][0] + b0) * cs, (acc[mt][j][1] + b1) * cs);
            if (r1 < M)
                *(uint32_t*)(p.out + (size_t)r1 * INNER + col) =
                    packbf((acc[mt][j][2] + b0) * cs, (acc[mt][j][3] + b1) * cs);
        }
    }
}

// ---------------- pipelined split-bf16 tail GEMM (256 threads) --------------
struct TArg {
    const __nv_bfloat16 *Ah, *Al, *Wh, *Wl;
    const float *bias, *res;
    float* Cf;
    __nv_bfloat16 *Ch, *Cl;
    int M, N, Kd, gelu;
};
#define TL_STG 32768

__global__ __launch_bounds__(256) void tail_gemm_kernel(TArg p)
{
    extern __shared__ char ts[];
    int tid = threadIdx.x, lane = tid & 31, warp = tid >> 5;
    int row0 = blockIdx.x * 64, col0 = blockIdx.y * 64;
    int wm = warp >> 1, wn = warp & 1;
    int nst = p.Kd >> 6;

    auto issue = [&](int st, int k0) {
        char* buf = ts + st * TL_STG;
#pragma unroll
        for (int i = 0; i < 2; i++) {
            int s = tid + i * 256;
            int r = s >> 3, c = s & 7;
            int ar = row0 + r; if (ar > p.M - 1) ar = p.M - 1;
            uint32_t doff = (uint32_t)(r * 128 + ((c ^ (r & 7)) << 4));
            size_t aoff = (size_t)ar * p.Kd + k0 + c * 8;
            size_t woff = (size_t)(k0 + r) * p.N + col0 + c * 8;
            CPA16(s2u(buf) + doff,         (const void*)(p.Ah + aoff));
            CPA16(s2u(buf) + 8192  + doff, (const void*)(p.Al + aoff));
            CPA16(s2u(buf) + 16384 + doff, (const void*)(p.Wh + woff));
            CPA16(s2u(buf) + 24576 + doff, (const void*)(p.Wl + woff));
        }
    };

    float acc[4][4];
#pragma unroll
    for (int j = 0; j < 4; j++)
#pragma unroll
        for (int x = 0; x < 4; x++) acc[j][x] = 0.f;

    issue(0, 0);
    CPC();

    for (int kt = 0; kt < nst; kt++) {
        if (kt + 1 < nst) { issue((kt + 1) & 1, (kt + 1) * 64); CPC(); CPW1(); }
        else              { CPW0(); }
        __syncthreads();
        char* sAh = ts + (kt & 1) * TL_STG;
        char* sAl = sAh + 8192;
        char* sWh = sAh + 16384;
        char* sWl = sAh + 24576;
#pragma unroll
        for (int kk = 0; kk < 4; kk++) {
            uint32_t ah[4], al[4];
            {
                int r = wm * 16 + (lane & 15);
                int koff = kk * 16 + ((lane & 16) ? 8 : 0);
                uint32_t sw = (uint32_t)(r * 128 + (((koff >> 3) ^ (r & 7)) << 4));
                LDSM4(ah[0], ah[1], ah[2], ah[3], s2u(sAh) + sw);
                LDSM4(al[0], al[1], al[2], al[3], s2u(sAl) + sw);
            }
            uint32_t wh[4][2], wl[4][2];
            int krow = kk * 16 + ((lane & 8) ? 8 : 0) + (lane & 7);
#pragma unroll
            for (int jj = 0; jj < 2; jj++) {
                int noff = wn * 32 + jj * 16 + ((lane & 16) ? 8 : 0);
                uint32_t sw = (uint32_t)(krow * 128 + (((noff >> 3) ^ (krow & 7)) << 4));
                LDSM4T(wh[2*jj][0], wh[2*jj][1], wh[2*jj+1][0], wh[2*jj+1][1], s2u(sWh) + sw);
                LDSM4T(wl[2*jj][0], wl[2*jj][1], wl[2*jj+1][0], wl[2*jj+1][1], s2u(sWl) + sw);
            }
#pragma unroll
            for (int j = 0; j < 4; j++) {
                MMA_BF16(acc[j], ah, wh[j][0], wh[j][1]);
                MMA_BF16(acc[j], ah, wl[j][0], wl[j][1]);
                MMA_BF16(acc[j], al, wh[j][0], wh[j][1]);
            }
        }
        __syncthreads();
    }

    int g = lane >> 2, c2 = (lane & 3) * 2;
    int rr[2];
    rr[0] = row0 + wm * 16 + g;
    rr[1] = rr[0] + 8;
#pragma unroll
    for (int j = 0; j < 4; j++) {
        int col = col0 + wn * 32 + j * 8 + c2;
        float b0 = p.bias[col], b1 = p.bias[col + 1];
#pragma unroll
        for (int half = 0; half < 2; half++) {
            int r = rr[half];
            if (r >= p.M) continue;
            float v0 = acc[j][2*half + 0] + b0;
            float v1 = acc[j][2*half + 1] + b1;
            if (p.gelu) {
                v0 = 0.5f * v0 * (1.0f + erff(v0 * 0.70710678118654752f));
                v1 = 0.5f * v1 * (1.0f + erff(v1 * 0.70710678118654752f));
            }
            if (p.res) {
                v0 += p.res[(size_t)r * p.N + col];
                v1 += p.res[(size_t)r * p.N + col + 1];
            }
            if (p.Cf)
                *(float2*)(p.Cf + (size_t)r * p.N + col) = make_float2(v0, v1);
            if (p.Ch) {
                float h0 = __bfloat162float(__float2bfloat16(v0));
                float h1 = __bfloat162float(__float2bfloat16(v1));
                *(uint32_t*)(p.Ch + (size_t)r * p.N + col) = packbf(v0, v1);
                *(uint32_t*)(p.Cl + (size_t)r * p.N + col) = packbf(v0 - h0, v1 - h1);
            }
        }
    }
}

// ---------------- bf16 HMMA flash cross-attention (compacted keys) ---------
// R15-proven configuration: L via ones-MMA on the tensor pipe.
#define QG_OFF   0
#define QA_OFF   8192
#define BUF0_OFF 16384
#define BUF_SZ   24832
#define B_KG     0
#define B_KA     8192
#define B_V      16384
#define B_MADD   24576
#define ATTN_SMEM (16384 + 2*BUF_SZ)   // 66048

__global__ __launch_bounds__(128) void attn_mma_kernel()
{
    extern __shared__ char sm_[];
    char* qg_s = sm_ + QG_OFF;
    char* qa_s = sm_ + QA_OFF;

    int tid = threadIdx.x, lane = tid & 31, warp = tid >> 5;
    int h  = blockIdx.y;
    int q0 = blockIdx.x * BQ;
    int sp = blockIdx.z;           // n-split
    int kbase = sp * KLEN;
    int ntl = g_ntiles[sp];
    const uint32_t ONESB = 0x3F803F80u;   // bf16x2 {1.0, 1.0}

#pragma unroll
    for (int i = 0; i < 4; i++) {
        int cidx = tid + i * 128;
        int r = cidx >> 3, c = cidx & 7;
        int q = q0 + r; if (q > QLEN - 1) q = QLEN - 1;
        uint32_t doff = (uint32_t)(r * 128 + ((c ^ (r & 7)) << 4));
        *(uint4*)(qa_s + doff) =
            *(const uint4*)(gb_qa + (size_t)q * INNER + h * DHEAD + c * 8);
        *(uint4*)(qg_s + doff) =
            *(const uint4*)(gb_qg + (size_t)(sp * QLEN + q) * INNER + h * DHEAD + c * 8);
    }

    auto issue = [&](char* buf, int t) {
        int r0 = kbase + t * BKT;
#pragma unroll
        for (int i = 0; i < 4; i++) {
            int cidx = tid + i * 128;
            int r = cidx >> 3, c = cidx & 7;
            uint32_t doff = (uint32_t)(r * 128 + ((c ^ (r & 7)) << 4));
            size_t goff = (size_t)(r0 + r) * INNER + h * DHEAD + c * 8;
            CPA16(s2u(buf) + B_KG + doff, (const void*)(gb_kg + goff));
            CPA16(s2u(buf) + B_KA + doff, (const void*)(gb_ka + goff));
            CPA16(s2u(buf) + B_V  + doff, (const void*)(gb_vv + goff));
        }
        if (tid < 16)
            CPA16(s2u(buf) + B_MADD + tid * 16, (const void*)(g_madd + r0 + tid * 4));
    };
    issue(sm_ + BUF0_OFF, 0);
    CPC();
    __syncthreads();

    uint32_t qa_f[4][4], qg_f[4][4];
    {
        int r = warp * 16 + (lane & 15);
#pragma unroll
        for (int kk = 0; kk < 4; kk++) {
            int koff = kk * 16 + ((lane & 16) ? 8 : 0);
            uint32_t sw = (uint32_t)(r * 128 + (((koff >> 3) ^ (r & 7)) << 4));
            LDSM4(qa_f[kk][0], qa_f[kk][1], qa_f[kk][2], qa_f[kk][3], s2u(qa_s) + sw);
            LDSM4(qg_f[kk][0], qg_f[kk][1], qg_f[kk][2], qg_f[kk][3], s2u(qg_s) + sw);
        }
    }

    float o[8][4];
#pragma unroll
    for (int j = 0; j < 8; j++)
#pragma unroll
        for (int x = 0; x < 4; x++) o[j][x] = 0.f;
    float lacc[4] = {0.f, 0.f, 0.f, 0.f};   // row sums via ones-MMA

    for (int t = 0; t < ntl; t++) {
        char* cbuf = sm_ + BUF0_OFF + (t & 1) * BUF_SZ;
        char* nbuf = sm_ + BUF0_OFF + ((t + 1) & 1) * BUF_SZ;

        if (t + 1 < ntl) { issue(nbuf, t + 1); CPC(); CPW1(); }
        else             { CPW0(); }
        __syncthreads();

        uint32_t kgb = s2u(cbuf) + B_KG;
        uint32_t kab = s2u(cbuf) + B_KA;
        uint32_t vb  = s2u(cbuf) + B_V;

        float s[8][4];
#pragma unroll
        for (int j = 0; j < 8; j++)
#pragma unroll
            for (int x = 0; x < 4; x++) s[j][x] = 0.f;

        int koff_b = ((lane & 8) ? 8 : 0);
        int nbase  = ((lane & 16) ? 8 : 0) + (lane & 7);
#pragma unroll
        for (int kk = 0; kk < 4; kk++) {
            int koff = kk * 16 + koff_b;
            uint32_t b[8][2];
#pragma unroll
            for (int jj = 0; jj < 4; jj++) {
                int n = jj * 16 + nbase;
                uint32_t a = kgb + n * 128 + (((koff >> 3) ^ (n & 7)) << 4);
                LDSM4(b[2*jj][0], b[2*jj][1], b[2*jj+1][0], b[2*jj+1][1], a);
            }
#pragma unroll
            for (int j = 0; j < 8; j++) MMA_BF16(s[j], qg_f[kk], b[j][0], b[j][1]);
#pragma unroll
            for (int jj = 0; jj < 4; jj++) {
                int n = jj * 16 + nbase;
                uint32_t a = kab + n * 128 + (((koff >> 3) ^ (n & 7)) << 4);
                LDSM4(b[2*jj][0], b[2*jj][1], b[2*jj+1][0], b[2*jj+1][1], a);
            }
#pragma unroll
            for (int j = 0; j < 8; j++) MMA_BF16(s[j], qa_f[kk], b[j][0], b[j][1]);
        }

        const float* madd = (const float*)(cbuf + B_MADD);
        int c0 = (lane & 3) * 2;
#pragma unroll
        for (int j = 0; j < 8; j++) {
            float2 md = *(const float2*)(madd + 8 * j + c0);
            s[j][0] = exp2f(s[j][0] + md.x);
            s[j][1] = exp2f(s[j][1] + md.y);
            s[j][2] = exp2f(s[j][2] + md.x);
            s[j][3] = exp2f(s[j][3] + md.y);
        }

        int nb = ((lane & 16) ? 8 : 0);
#pragma unroll
        for (int kk = 0; kk < 4; kk++) {
            uint32_t a[4];
            a[0] = packbf(s[2*kk][0],   s[2*kk][1]);
            a[1] = packbf(s[2*kk][2],   s[2*kk][3]);
            a[2] = packbf(s[2*kk+1][0], s[2*kk+1][1]);
            a[3] = packbf(s[2*kk+1][2], s[2*kk+1][3]);
            int krow = kk * 16 + ((lane & 8) ? 8 : 0) + (lane & 7);
            uint32_t b[8][2];
#pragma unroll
            for (int jj = 0; jj < 4; jj++) {
                int noff = jj * 16 + nb;
                uint32_t ad = vb + krow * 128 + (((noff >> 3) ^ (krow & 7)) << 4);
                LDSM4T(b[2*jj][0], b[2*jj][1], b[2*jj+1][0], b[2*jj+1][1], ad);
            }
#pragma unroll
            for (int j = 0; j < 8; j++) MMA_BF16(o[j], a, b[j][0], b[j][1]);
            MMA_BF16(lacc, a, ONESB, ONESB);
        }
        __syncthreads();
    }

    int g = lane >> 2, c0 = (lane & 3) * 2;
    int r0q = q0 + warp * 16 + g;
    int r1q = r0q + 8;
    __nv_bfloat16* po = g_po_bf + (size_t)((sp * HEADS + h) * QLEN) * DHEAD;
    float* pl = g_pl + (sp * HEADS + h) * QLEN;
    if (r0q < QLEN) {
#pragma unroll
        for (int j = 0; j < 8; j++)
            *(uint32_t*)(po + (size_t)r0q * DHEAD + 8 * j + c0) =
                packbf(o[j][0], o[j][1]);
        if ((lane & 3) == 0) pl[r0q] = lacc[0];
    }
    if (r1q < QLEN) {
#pragma unroll
        for (int j = 0; j < 8; j++)
            *(uint32_t*)(po + (size_t)r1q * DHEAD + 8 * j + c0) =
                packbf(o[j][2], o[j][3]);
        if ((lane & 3) == 0) pl[r1q] = lacc[2];
    }
}

// ---------------- combine partials (fine-grained) -> att hi/lo bf16 --------
// one thread per 4-element d-chunk: 900*8*16 = 115200 threads.
__global__ __launch_bounds__(128) void combine_kernel()
{
    int gt = blockIdx.x * 128 + threadIdx.x;
    if (gt >= QLEN * HEADS * 16) return;
    int q  = gt >> 7;
    int r  = gt & 127;
    int h  = r >> 4;
    int ch = r & 15;

    float O[4] = {0.f, 0.f, 0.f, 0.f};
    float L = 0.f;
#pragma unroll
    for (int s = 0; s < NN; s++) {
        int idx = (s * HEADS + h) * QLEN + q;
        L += g_pl[idx];
        uint2 w = *(const uint2*)(g_po_bf + (size_t)idx * DHEAD + ch * 4);
        float2 f;
        f = unpackbf(w.x); O[0] += f.x; O[1] += f.y;
        f = unpackbf(w.y); O[2] += f.x; O[3] += f.y;
    }
    float inv = 1.0f / L;
    uint32_t hw[2], lw[2];
#pragma unroll
    for (int i = 0; i < 2; i++) {
        float v0 = O[2*i] * inv, v1 = O[2*i+1] * inv;
        float h0 = __bfloat162float(__float2bfloat16(v0));
        float h1 = __bfloat162float(__float2bfloat16(v1));
        hw[i] = packbf(v0, v1);
        lw[i] = packbf(v0 - h0, v1 - h1);
    }
    size_t oidx = (size_t)q * INNER + h * DHEAD + ch * 4;
    *(uint2*)(ga_h + oidx) = make_uint2(hw[0], hw[1]);
    *(uint2*)(ga_l + oidx) = make_uint2(lw[0], lw[1]);
}

// ---------------- LayerNorm (optional hi/lo bf16 side output) --------------
__global__ __launch_bounds__(256) void ln_kernel(
    const float* __restrict__ x, const float* __restrict__ g,
    const float* __restrict__ b, float* __restrict__ y,
    __nv_bfloat16* __restrict__ yh, __nv_bfloat16* __restrict__ yl)
{
    int row = blockIdx.x;
    int tid = threadIdx.x;
    float v = x[(size_t)row * DIMV + tid];
    float s = v, s2 = v * v;
#pragma unroll
    for (int off = 16; off > 0; off >>= 1) {
        s  += __shfl_xor_sync(0xffffffffu, s, off);
        s2 += __shfl_xor_sync(0xffffffffu, s2, off);
    }
    __shared__ float rs[8], rs2[8];
    int w = tid >> 5;
    if ((tid & 31) == 0) { rs[w] = s; rs2[w] = s2; }
    __syncthreads();
    float ts = 0.f, ts2 = 0.f;
#pragma unroll
    for (int i = 0; i < 8; i++) { ts += rs[i]; ts2 += rs2[i]; }
    float mean = ts * (1.0f / DIMV);
    float var  = ts2 * (1.0f / DIMV) - mean * mean;
    float val = (v - mean) * rsqrtf(var + 1e-5f) * g[tid] + b[tid];
    y[(size_t)row * DIMV + tid] = val;
    if (yh) {
        __nv_bfloat16 hi = __float2bfloat16(val);
        yh[(size_t)row * DIMV + tid] = hi;
        yl[(size_t)row * DIMV + tid] = __float2bfloat16(val - __bfloat162float(hi));
    }
}

// ---------------- launcher ------------------------------------------------
extern "C" void kernel_launch(void* const* d_in, const int* in_sizes, int n_in,
                              void* d_out, int out_size)
{
    (void)in_sizes; (void)n_in; (void)out_size;
    const float* k_g  = (const float*)d_in[0];
    const float* q_g  = (const float*)d_in[1];
    const float* k_a  = (const float*)d_in[2];
    const float* q_a  = (const float*)d_in[3];
    const float* v    = (const float*)d_in[4];
    const unsigned char* mask = (const unsigned char*)d_in[5];
    const float* W_qg = (const float*)d_in[6];
    const float* b_qg = (const float*)d_in[7];
    const float* W_kg = (const float*)d_in[8];
    const float* b_kg = (const float*)d_in[9];
    const float* W_qa = (const float*)d_in[10];
    const float* b_qa = (const float*)d_in[11];
    const float* W_ka = (const float*)d_in[12];
    const float* b_ka = (const float*)d_in[13];
    const float* W_v  = (const float*)d_in[14];
    const float* b_v  = (const float*)d_in[15];
    const float* W_o  = (const float*)d_in[16];
    const float* b_o  = (const float*)d_in[17];
    const float* ln1_g = (const float*)d_in[18];
    const float* ln1_b = (const float*)d_in[19];
    const float* W_m1 = (const float*)d_in[20];
    const float* b_m1 = (const float*)d_in[21];
    const float* W_m2 = (const float*)d_in[22];
    const float* b_m2 = (const float*)d_in[23];
    const float* ln2_g = (const float*)d_in[24];
    const float* ln2_b = (const float*)d_in[25];
    const float* scale_g = (const float*)d_in[26];
    const float* scale_a = (const float*)d_in[27];
    float* out = (float*)d_out;

    __nv_bfloat16 *pb_qg, *pb_kg, *pb_ka, *pb_qa, *pb_vv;
    __nv_bfloat16 *pi_qg, *pi_qa, *pi_kg, *pi_ka, *pi_v;
    __nv_bfloat16 *pw_qg, *pw_kg, *pw_qa, *pw_ka, *pw_v;
    __nv_bfloat16 *pah, *pal, *pz1h, *pz1l, *ph1h, *ph1l;
    __nv_bfloat16 *pwoh, *pwol, *pwm1h, *pwm1l, *pwm2h, *pwm2l;
    float *p_z0, *p_z1, *p_z2;
    int *p_kidx, *p_ntl;
    cudaGetSymbolAddress((void**)&pb_qg, gb_qg);
    cudaGetSymbolAddress((void**)&pb_kg, gb_kg);
    cudaGetSymbolAddress((void**)&pb_ka, gb_ka);
    cudaGetSymbolAddress((void**)&pb_qa, gb_qa);
    cudaGetSymbolAddress((void**)&pb_vv, gb_vv);
    cudaGetSymbolAddress((void**)&pi_qg, gbi_qg);
    cudaGetSymbolAddress((void**)&pi_qa, gbi_qa);
    cudaGetSymbolAddress((void**)&pi_kg, gbi_kg);
    cudaGetSymbolAddress((void**)&pi_ka, gbi_ka);
    cudaGetSymbolAddress((void**)&pi_v,  gbi_v);
    cudaGetSymbolAddress((void**)&pw_qg, gbw_qg);
    cudaGetSymbolAddress((void**)&pw_kg, gbw_kg);
    cudaGetSymbolAddress((void**)&pw_qa, gbw_qa);
    cudaGetSymbolAddress((void**)&pw_ka, gbw_ka);
    cudaGetSymbolAddress((void**)&pw_v,  gbw_v);
    cudaGetSymbolAddress((void**)&pah,   ga_h);
    cudaGetSymbolAddress((void**)&pal,   ga_l);
    cudaGetSymbolAddress((void**)&pz1h,  gz1_h);
    cudaGetSymbolAddress((void**)&pz1l,  gz1_l);
    cudaGetSymbolAddress((void**)&ph1h,  gh1_h);
    cudaGetSymbolAddress((void**)&ph1l,  gh1_l);
    cudaGetSymbolAddress((void**)&pwoh,  gwo_h);
    cudaGetSymbolAddress((void**)&pwol,  gwo_l);
    cudaGetSymbolAddress((void**)&pwm1h, gwm1_h);
    cudaGetSymbolAddress((void**)&pwm1l, gwm1_l);
    cudaGetSymbolAddress((void**)&pwm2h, gwm2_h);
    cudaGetSymbolAddress((void**)&pwm2l, gwm2_l);
    cudaGetSymbolAddress((void**)&p_z0,  g_z0);
    cudaGetSymbolAddress((void**)&p_z1,  g_z1);
    cudaGetSymbolAddress((void**)&p_z2,  g_z2);
    cudaGetSymbolAddress((void**)&p_kidx, g_kidx);
    cudaGetSymbolAddress((void**)&p_ntl,  g_ntiles);

    dim3 blk(256);

    CvtTable ct;
    const float* srcs[NCVT]   = {q_g, q_a, k_g, k_a, v,
                                 W_qg, W_kg, W_qa, W_ka, W_v,
                                 W_o, W_m1, W_m2};
    __nv_bfloat16* dsts[NCVT] = {pi_qg, pi_qa, pi_kg, pi_ka, pi_v,
                                 pw_qg, pw_kg, pw_qa, pw_ka, pw_v,
                                 pwoh, pwm1h, pwm2h};
    __nv_bfloat16* dstl[NCVT] = {nullptr, nullptr, nullptr, nullptr, nullptr,
                                 nullptr, nullptr, nullptr, nullptr, nullptr,
                                 pwol, pwm1l, pwm2l};
    int sizes4[NCVT] = {NQG*DIMV/4, QLEN*DIMV/4, NK*DIMV/4, NK*DIMV/4, NK*DIMV/4,
                        DIMV*INNER/4, DIMV*INNER/4, DIMV*INNER/4, DIMV*INNER/4, DIMV*INNER/4,
                        INNER*DIMV/4, DIMV*INNER/4, INNER*DIMV/4};
    ct.off[0] = 0;
    for (int i = 0; i < NCVT; i++) {
        ct.src[i]  = srcs[i];
        ct.dst[i]  = dsts[i];
        ct.dstl[i] = dstl[i];
        ct.off[i+1] = ct.off[i] + sizes4[i];
    }
    cvt_kernel<<<4352 + NN, blk>>>(ct, mask);

    {
        PArg a0 = {pi_kg, pw_kg, b_kg, nullptr, 1.0f,  pb_kg, p_kidx, p_ntl, NK};
        PArg a1 = {pi_ka, pw_ka, b_ka, nullptr, 1.0f,  pb_ka, p_kidx, p_ntl, NK};
        PArg a2 = {pi_v,  pw_v,  b_v,  nullptr, 1.0f,  pb_vv, p_kidx, p_ntl, NK};
        PArg a3 = {pi_qg, pw_qg, b_qg, scale_g, LOG2E, pb_qg, nullptr, nullptr, NQG};
        PArg a4 = {pi_qa, pw_qa, b_qa, scale_a, LOG2E, pb_qa, nullptr, nullptr, QLEN};
        proj_gemm_kernel<<<dim3(NK/128, INNER/64, 5), blk>>>(a0, a1, a2, a3, a4);
    }

    cudaFuncSetAttribute(attn_mma_kernel, cudaFuncAttributeMaxDynamicSharedMemorySize, ATTN_SMEM);
    attn_mma_kernel<<<dim3((QLEN + BQ - 1) / BQ, HEADS, NN), 128, ATTN_SMEM>>>();
    combine_kernel<<<(QLEN * HEADS * 16 + 127) / 128, 128>>>();

    cudaFuncSetAttribute(tail_gemm_kernel, cudaFuncAttributeMaxDynamicSharedMemorySize, 2 * TL_STG);
    {
        TArg t1 = {pah, pal, pwoh, pwol, b_o, q_a, p_z0, nullptr, nullptr,
                   QLEN, DIMV, INNER, 0};
        tail_gemm_kernel<<<dim3((QLEN + 63)/64, DIMV/64), blk, 2 * TL_STG>>>(t1);
    }
    ln_kernel<<<QLEN, DIMV>>>(p_z0, ln1_g, ln1_b, p_z1, pz1h, pz1l);
    {
        TArg t2 = {pz1h, pz1l, pwm1h, pwm1l, b_m1, nullptr, nullptr, ph1h, ph1l,
                   QLEN, INNER, DIMV, 1};
        tail_gemm_kernel<<<dim3((QLEN + 63)/64, INNER/64), blk, 2 * TL_STG>>>(t2);
    }
    {
        TArg t3 = {ph1h, ph1l, pwm2h, pwm2l, b_m2, p_z1, p_z2, nullptr, nullptr,
                   QLEN, DIMV, INNER, 0};
        tail_gemm_kernel<<<dim3((QLEN + 63)/64, DIMV/64), blk, 2 * TL_STG>>>(t3);
    }
    ln_kernel<<<QLEN, DIMV>>>(p_z2, ln2_g, ln2_b, out, nullptr, nullptr);
}